// round 16
// baseline (speedup 1.0000x reference)
#include <cuda_runtime.h>
#include <cuda_bf16.h>
#include <math.h>
#include <stdint.h>

// ---------------- problem constants ----------------
constexpr int kT = 2048;
constexpr int kB = 2;
constexpr int kE = 1024;
constexpr int kH = 8;
constexpr int kD = 128;
constexpr int kR = 2;
constexpr int kNH = 8;
constexpr int kCH = 32;
constexpr int kC = kT / kCH;  // 64
constexpr int kM = 3 * kCH;   // 96
constexpr int kTB = kT * kB;  // 4096

constexpr float kScale = 0.08838834764831845f;  // D^-0.5
constexpr float kInfM = 1.0e16f;
constexpr float kBigM = 1.0e8f;
constexpr float kLog2 = 0.6931471805599453f;

// ---------------- device scratch ----------------
__device__ float g_QF[kTB * kE];
__device__ float g_o[kB * kR * kH * kT * kD];
__device__ float g_z[kB * kR * kH * kT];
__device__ int g_hash[kTB * 16];  // [tb][r*8+h]
__device__ int g_pq[kB * kR * kH * kT];
__device__ int g_invq[kB * kR * kH * kT];
__device__ unsigned g_mask[kB * kR * kH * kC * (kT / 32)];
__device__ float g_Mq[kE * 64];
__device__ float g_cq[64];
// bf16 hi/lo operand splits
__device__ __nv_bfloat16 g_Ahi[kTB * kE];   // query / combined-out splits
__device__ __nv_bfloat16 g_Alo[kTB * kE];
__device__ __nv_bfloat16 g_Vihi[kTB * kE];  // raw value input splits
__device__ __nv_bfloat16 g_Vilo[kTB * kE];
// projected tensors, bf16 hi/lo (consumed by attention)
__device__ __nv_bfloat16 g_Q16h[kTB * kE];
__device__ __nv_bfloat16 g_Q16l[kTB * kE];
__device__ __nv_bfloat16 g_K16h[kTB * kE];
__device__ __nv_bfloat16 g_K16l[kTB * kE];
__device__ __nv_bfloat16 g_V16h[kTB * kE];
__device__ __nv_bfloat16 g_V16l[kTB * kE];
// transposed + hi/lo split weights, [N=1024][K=1024]
__device__ __nv_bfloat16 g_WqThi[kE * kE];
__device__ __nv_bfloat16 g_WqTlo[kE * kE];
__device__ __nv_bfloat16 g_WvThi[kE * kE];
__device__ __nv_bfloat16 g_WvTlo[kE * kE];
__device__ __nv_bfloat16 g_WoThi[kE * kE];
__device__ __nv_bfloat16 g_WoTlo[kE * kE];

// ---------------- helpers ----------------
__device__ __forceinline__ uint32_t smem_u32(const void* p) {
  uint32_t a;
  asm("{ .reg .u64 t; cvta.to.shared.u64 t, %1; cvt.u32.u64 %0, t; }"
      : "=r"(a) : "l"(p));
  return a;
}
__device__ __forceinline__ void ldsm_x4(uint32_t* r, uint32_t addr) {
  asm volatile(
      "ldmatrix.sync.aligned.m8n8.x4.shared.b16 {%0,%1,%2,%3}, [%4];"
      : "=r"(r[0]), "=r"(r[1]), "=r"(r[2]), "=r"(r[3]) : "r"(addr));
}
__device__ __forceinline__ void ldsm_x2(uint32_t* r, uint32_t addr) {
  asm volatile(
      "ldmatrix.sync.aligned.m8n8.x2.shared.b16 {%0,%1}, [%2];"
      : "=r"(r[0]), "=r"(r[1]) : "r"(addr));
}
__device__ __forceinline__ void ldsm_x2t(uint32_t* r, uint32_t addr) {
  asm volatile(
      "ldmatrix.sync.aligned.m8n8.x2.trans.shared.b16 {%0,%1}, [%2];"
      : "=r"(r[0]), "=r"(r[1]) : "r"(addr));
}
__device__ __forceinline__ void mma16816(float* d, const uint32_t* a,
                                         const uint32_t* b) {
  asm volatile(
      "mma.sync.aligned.m16n8k16.row.col.f32.bf16.bf16.f32 "
      "{%0,%1,%2,%3}, {%4,%5,%6,%7}, {%8,%9}, {%0,%1,%2,%3};"
      : "+f"(d[0]), "+f"(d[1]), "+f"(d[2]), "+f"(d[3])
      : "r"(a[0]), "r"(a[1]), "r"(a[2]), "r"(a[3]), "r"(b[0]), "r"(b[1]));
}
__device__ __forceinline__ void cp16(uint32_t dst, const void* src) {
  asm volatile("cp.async.cg.shared.global [%0], [%1], 16;" ::"r"(dst),
               "l"(src));
}
__device__ __forceinline__ void split_bf16(float v, __nv_bfloat16& h,
                                           __nv_bfloat16& l) {
  h = __float2bfloat16(v);
  l = __float2bfloat16(v - __bfloat162float(h));
}

// ---------------- A fp32 -> bf16 hi/lo split ----------------
__global__ __launch_bounds__(256) void asplit_kernel(
    const float* __restrict__ A, __nv_bfloat16* __restrict__ outhi,
    __nv_bfloat16* __restrict__ outlo) {
  int idx = blockIdx.x * 256 + threadIdx.x;
  float4 v = ((const float4*)A)[idx];
  __nv_bfloat16 h0, h1, h2, h3, l0, l1, l2, l3;
  split_bf16(v.x, h0, l0);
  split_bf16(v.y, h1, l1);
  split_bf16(v.z, h2, l2);
  split_bf16(v.w, h3, l3);
  __nv_bfloat162 ph0 = {h0, h1}, ph1 = {h2, h3};
  __nv_bfloat162 pl0 = {l0, l1}, pl1 = {l2, l3};
  uint2 uh = {*(uint32_t*)&ph0, *(uint32_t*)&ph1};
  uint2 ul = {*(uint32_t*)&pl0, *(uint32_t*)&pl1};
  ((uint2*)outhi)[idx] = uh;
  ((uint2*)outlo)[idx] = ul;
}

// ---------------- weight transpose + bf16 hi/lo split ----------------
__global__ __launch_bounds__(256) void wsplit_kernel(
    const float* __restrict__ W, __nv_bfloat16* __restrict__ hi,
    __nv_bfloat16* __restrict__ lo) {
  __shared__ float t[32][33];
  int bx = blockIdx.x * 32;
  int by = blockIdx.y * 32;
  int x = threadIdx.x, y = threadIdx.y;
#pragma unroll
  for (int i = 0; i < 32; i += 8)
    t[y + i][x] = W[(size_t)(by + y + i) * kE + bx + x];
  __syncthreads();
#pragma unroll
  for (int i = 0; i < 32; i += 8) {
    float v = t[x][y + i];
    __nv_bfloat16 h, l;
    split_bf16(v, h, l);
    size_t o = (size_t)(bx + y + i) * kE + by + x;
    hi[o] = h;
    lo[o] = l;
  }
}

// ---------------- bf16x3 HMMA GEMM (4 warps, 64x64 warp tiles) ----------------
constexpr int kTileB = 128 * 80;
constexpr int kStageB = 4 * kTileB;
constexpr int kGSmem = 2 * kStageB;  // 81920

__global__ __launch_bounds__(128) void gemm_mma(
    const __nv_bfloat16* __restrict__ Ahi, const __nv_bfloat16* __restrict__ Alo,
    const __nv_bfloat16* __restrict__ Bhi, const __nv_bfloat16* __restrict__ Blo,
    const float* __restrict__ bias, float* __restrict__ Cfp,
    __nv_bfloat16* __restrict__ Chi, __nv_bfloat16* __restrict__ Clo) {
  extern __shared__ char smc[];
  uint32_t sbase = smem_u32(smc);
  int tid = threadIdx.x;
  int lane = tid & 31, wid = tid >> 5;
  int row0 = blockIdx.y * 128, col0 = blockIdx.x * 128;
  int m0w = (wid >> 1) * 64, n0w = (wid & 1) * 64;

  float acc[4][8][4];
#pragma unroll
  for (int i = 0; i < 4; i++)
#pragma unroll
    for (int j = 0; j < 8; j++)
#pragma unroll
      for (int q = 0; q < 4; q++) acc[i][j][q] = 0.f;

  const __nv_bfloat16* srcs[4] = {Ahi, Alo, Bhi, Blo};

  auto issue = [&](int ch, int s) {
    int k0 = ch * 32;
#pragma unroll
    for (int t = 0; t < 4; t++) {
      const __nv_bfloat16* src = srcs[t];
      int base0 = (t < 2) ? row0 : col0;
#pragma unroll
      for (int i = 0; i < 4; i++) {
        int idx = tid + i * 128;
        int row = idx >> 2, seg = idx & 3;
        uint32_t dst = sbase + s * kStageB + t * kTileB + row * 80 + seg * 16;
        cp16(dst, src + (size_t)(base0 + row) * kE + k0 + seg * 8);
      }
    }
    asm volatile("cp.async.commit_group;");
  };

  issue(0, 0);
  for (int ch = 0; ch < 32; ch++) {
    int s = ch & 1;
    if (ch + 1 < 32) {
      issue(ch + 1, s ^ 1);
      asm volatile("cp.async.wait_group 1;");
    } else {
      asm volatile("cp.async.wait_group 0;");
    }
    __syncthreads();
    uint32_t abase = sbase + s * kStageB;
    uint32_t bbase = sbase + s * kStageB + 2 * kTileB;
#pragma unroll
    for (int k16 = 0; k16 < 2; k16++) {
      uint32_t a_hi[4][4], a_lo[4][4], bf[8][2];
      uint32_t aoff = (k16 * 16 + (lane >> 4) * 8) * 2;
#pragma unroll
      for (int mt = 0; mt < 4; mt++) {
        uint32_t ra = (m0w + mt * 16 + (lane & 15)) * 80 + aoff;
        ldsm_x4(a_hi[mt], abase + ra);
        ldsm_x4(a_lo[mt], abase + kTileB + ra);
      }
      // B hi: x4 per n-tile pair (mat0/1 = nt pair at k-half0, mat2/3 at half1)
      uint32_t rbq = (n0w + ((lane >> 3) & 1) * 8 + (lane & 7)) * 80 + aoff;
#pragma unroll
      for (int p = 0; p < 4; p++) {
        uint32_t q4[4];
        ldsm_x4(q4, bbase + rbq + p * 16 * 80);
        bf[2 * p][0] = q4[0];
        bf[2 * p][1] = q4[2];
        bf[2 * p + 1][0] = q4[1];
        bf[2 * p + 1][1] = q4[3];
      }
#pragma unroll
      for (int mt = 0; mt < 4; mt++)
#pragma unroll
        for (int nt = 0; nt < 8; nt++) mma16816(acc[mt][nt], a_hi[mt], bf[nt]);
#pragma unroll
      for (int mt = 0; mt < 4; mt++)
#pragma unroll
        for (int nt = 0; nt < 8; nt++) mma16816(acc[mt][nt], a_lo[mt], bf[nt]);
      // B lo
#pragma unroll
      for (int p = 0; p < 4; p++) {
        uint32_t q4[4];
        ldsm_x4(q4, bbase + kTileB + rbq + p * 16 * 80);
        bf[2 * p][0] = q4[0];
        bf[2 * p][1] = q4[2];
        bf[2 * p + 1][0] = q4[1];
        bf[2 * p + 1][1] = q4[3];
      }
#pragma unroll
      for (int mt = 0; mt < 4; mt++)
#pragma unroll
        for (int nt = 0; nt < 8; nt++) mma16816(acc[mt][nt], a_hi[mt], bf[nt]);
    }
    __syncthreads();
  }
#pragma unroll
  for (int mt = 0; mt < 4; mt++) {
#pragma unroll
    for (int nt = 0; nt < 8; nt++) {
      int r = row0 + m0w + mt * 16 + (lane >> 2);
      int cc = col0 + n0w + nt * 8 + (lane & 3) * 2;
      float2 b0 = *(const float2*)(bias + cc);
      float v0 = acc[mt][nt][0] + b0.x, v1 = acc[mt][nt][1] + b0.y;
      float v2 = acc[mt][nt][2] + b0.x, v3 = acc[mt][nt][3] + b0.y;
      if (Cfp) {
        *(float2*)(Cfp + (size_t)r * kE + cc) = {v0, v1};
        *(float2*)(Cfp + (size_t)(r + 8) * kE + cc) = {v2, v3};
      } else {
        __nv_bfloat16 h0, h1, h2, h3, l0, l1, l2, l3;
        split_bf16(v0, h0, l0);
        split_bf16(v1, h1, l1);
        split_bf16(v2, h2, l2);
        split_bf16(v3, h3, l3);
        *(__nv_bfloat162*)(Chi + (size_t)r * kE + cc) = {h0, h1};
        *(__nv_bfloat162*)(Clo + (size_t)r * kE + cc) = {l0, l1};
        *(__nv_bfloat162*)(Chi + (size_t)(r + 8) * kE + cc) = {h2, h3};
        *(__nv_bfloat162*)(Clo + (size_t)(r + 8) * kE + cc) = {l2, l3};
      }
    }
  }
}

// ---------------- exact hash path ----------------
constexpr int kPrepSmem = (128 * 132 + 512) * 4;
__global__ __launch_bounds__(128) void prepM_kernel(
    const float* __restrict__ Wq, const float* __restrict__ bq,
    const float* __restrict__ hw) {
  extern __shared__ float ps[];
  float* wtile = ps;
  float* hws = ps + 128 * 132;
  int rh = blockIdx.x, ec = blockIdx.y;
  int h = rh & 7;
  int tid = threadIdx.x;
  for (int i = tid; i < 128; i += 128)
    *(float4*)&hws[i * 4] = *(const float4*)&hw[rh * 512 + i * 4];
#pragma unroll
  for (int it = 0; it < 32; it++) {
    int i = tid + it * 128;
    int row = i >> 5, c4 = i & 31;
    float4 v = *(const float4*)(Wq + (size_t)(ec * 128 + row) * kE + h * kD +
                                c4 * 4);
    *(float4*)&wtile[row * 132 + c4 * 4] = v;
  }
  __syncthreads();
  float s0 = 0.f, s1 = 0.f, s2 = 0.f, s3 = 0.f;
  const float* wr = wtile + tid * 132;
#pragma unroll 4
  for (int d = 0; d < kD; d++) {
    float w = wr[d];
    s0 += w * hws[d * 4 + 0];
    s1 += w * hws[d * 4 + 1];
    s2 += w * hws[d * 4 + 2];
    s3 += w * hws[d * 4 + 3];
  }
  float4 o = {s0, s1, s2, s3};
  *(float4*)(g_Mq + (size_t)(ec * 128 + tid) * 64 + rh * 4) = o;
  if (ec == 0 && tid < 4) {
    float c = 0.f;
    for (int d = 0; d < kD; d++) c += bq[h * kD + d] * hws[d * 4 + tid];
    g_cq[rh * 4 + tid] = c;
  }
}

__global__ __launch_bounds__(256) void linhash_kernel(
    const float* __restrict__ query) {
  __shared__ float slin[8][64];
  int warp = threadIdx.x >> 5, lane = threadIdx.x & 31;
  int tb = blockIdx.x * 8 + warp;
  float acc0 = g_cq[lane], acc1 = g_cq[lane + 32];
  for (int e0 = 0; e0 < kE; e0 += 32) {
    float xv = query[(size_t)tb * kE + e0 + lane];
#pragma unroll
    for (int l2 = 0; l2 < 32; l2++) {
      float v = __shfl_sync(0xffffffffu, xv, l2);
      acc0 += v * g_Mq[(e0 + l2) * 64 + lane];
      acc1 += v * g_Mq[(e0 + l2) * 64 + lane + 32];
    }
  }
  slin[warp][lane] = acc0;
  slin[warp][lane + 32] = acc1;
  __syncwarp();
  if (lane < 16) {
    const float* p = &slin[warp][lane * 4];
    float best = p[0];
    int bi = 0;
#pragma unroll
    for (int n = 1; n < 4; n++)
      if (p[n] > best) { best = p[n]; bi = n; }
#pragma unroll
    for (int n = 0; n < 4; n++)
      if (-p[n] > best) { best = -p[n]; bi = 4 + n; }
    g_hash[tb * 16 + lane] = bi;
  }
}

// ---------------- normalize + scale -> bf16 hi/lo ----------------
__global__ __launch_bounds__(256) void normalize_kernel() {
  int row = blockIdx.x;
  const float* x = g_QF + (size_t)row * kE;
  __shared__ float red[256];
  int tid = threadIdx.x;
  float s = 0.f;
#pragma unroll
  for (int i = 0; i < 4; i++) {
    float v = x[tid + i * 256];
    s += v * v;
  }
  red[tid] = s;
  __syncthreads();
  for (int off = 128; off > 0; off >>= 1) {
    if (tid < off) red[tid] += red[tid + off];
    __syncthreads();
  }
  float invn = 1.0f / sqrtf(red[0]);
#pragma unroll
  for (int i = 0; i < 4; i++) {
    int e = tid + i * 256;
    float v = x[e];
    size_t o = (size_t)row * kE + e;
    __nv_bfloat16 h, l;
    split_bf16(v * kScale, h, l);
    g_Q16h[o] = h;
    g_Q16l[o] = l;
    split_bf16(v * invn, h, l);
    g_K16h[o] = h;
    g_K16l[o] = l;
  }
}

// ---------------- stable counting sort per (b,r,h), scan-based ----------------
__global__ __launch_bounds__(256) void sort_kernel() {
  int brh = blockIdx.x;
  int h = brh & 7;
  int r = (brh >> 3) & 1;
  int b = brh >> 4;
  __shared__ int cntmat[kNH][256];
  __shared__ int btot[kNH];
  __shared__ int bbase[kNH];
  int tid = threadIdx.x;
  int w = tid >> 5, lane = tid & 31;

  int vals[8];
  int cnt[kNH];
#pragma unroll
  for (int i = 0; i < kNH; i++) cnt[i] = 0;
#pragma unroll
  for (int i = 0; i < 8; i++) {
    int t = tid * 8 + i;
    int v = g_hash[(t * kB + b) * 16 + r * 8 + h];
    vals[i] = v;
    cnt[v]++;
  }
#pragma unroll
  for (int i = 0; i < kNH; i++) cntmat[i][tid] = cnt[i];
  __syncthreads();
  {
    int run = 0;
#pragma unroll
    for (int chk = 0; chk < 8; chk++) {
      int orig = cntmat[w][chk * 32 + lane];
      int x = orig;
#pragma unroll
      for (int off = 1; off < 32; off <<= 1) {
        int y = __shfl_up_sync(0xffffffffu, x, off);
        if (lane >= off) x += y;
      }
      cntmat[w][chk * 32 + lane] = run + x - orig;
      run += __shfl_sync(0xffffffffu, x, 31);
    }
    if (lane == 0) btot[w] = run;
  }
  __syncthreads();
  if (tid == 0) {
    int s = 0;
    for (int i = 0; i < kNH; i++) {
      bbase[i] = s;
      s += btot[i];
    }
  }
  __syncthreads();
  int off[kNH];
#pragma unroll
  for (int i = 0; i < kNH; i++) off[i] = bbase[i] + cntmat[i][tid];
#pragma unroll
  for (int i = 0; i < 8; i++) {
    int v = vals[i];
    int pos = off[v]++;
    int t = tid * 8 + i;
    g_pq[brh * kT + pos] = t;
    g_invq[brh * kT + t] = pos;
  }
}

// ---------------- per-chunk window bitmask ----------------
__global__ __launch_bounds__(128) void mask_kernel() {
  int blk = blockIdx.x;
  int c = blk & (kC - 1);
  int brh = blk >> 6;
  unsigned* mw = g_mask + (size_t)blk * (kT / 32);
  int tid = threadIdx.x;
  if (tid < kT / 32) mw[tid] = 0u;
  __syncthreads();
  if (tid < kM) {
    int cc2 = (c + (tid >> 5) + kC - 1) & (kC - 1);
    int pos = cc2 * kCH + (tid & 31);
    int id = g_pq[brh * kT + pos];
    atomicOr(&mw[id >> 5], 1u << (id & 31));
  }
}

// ---------------- attention (HMMA bf16x3 scores + output) ----------------
constexpr int kQKS = 272;
constexpr int kPS = 208;
constexpr int kSCS = 100;
constexpr int ATTN_SMEM = 97152;

__global__ __launch_bounds__(256, 2) void attn_kernel() {
  extern __shared__ char smb[];
  uint32_t sb = smem_u32(smb);
  float* sc = (float*)(smb + 69632);
  float* rinv = (float*)(smb + 95744);
  float* rowz = (float*)(smb + 95872);
  int* qid = (int*)(smb + 96000);
  int* qhh = (int*)(smb + 96128);
  int* oc2 = (int*)(smb + 96256);
  int* kid = (int*)(smb + 96384);
  int* khh = (int*)(smb + 96768);

  int blk = blockIdx.x;
  int c = blk & (kC - 1);
  int brh = blk >> 6;
  int h = brh & 7;
  int r = (brh >> 3) & 1;
  int b = brh >> 4;
  int brho = (b * kR + (1 - r)) * kH + h;
  int tid = threadIdx.x;
  int lane = tid & 31, w = tid >> 5;

  if (tid < 32) {
    int ts = c * kCH + tid;
    int tok = g_pq[brh * kT + ts];
    qid[tid] = tok;
    qhh[tid] = g_hash[(tok * kB + b) * 16 + r * 8 + h];
    oc2[tid] = g_invq[brho * kT + tok] >> 5;
  } else if (tid < 128) {
    int m = tid - 32;
    int cc2 = (c + (m >> 5) + kC - 1) & (kC - 1);
    int pos = cc2 * kCH + (m & 31);
    int tokk = g_pq[brh * kT + pos];
    kid[m] = tokk;
    khh[m] = g_hash[(tokk * kB + b) * 16 + r * 8 + h];
  }
  __syncthreads();

#pragma unroll
  for (int i = 0; i < 2; i++) {
    int idx = tid + i * 256;
    int row = idx >> 4, seg = idx & 15;
    size_t src = (size_t)(qid[row] * kB + b) * kE + h * kD + seg * 8;
    cp16(sb + row * kQKS + seg * 16, g_Q16h + src);
    cp16(sb + 8704 + row * kQKS + seg * 16, g_Q16l + src);
  }
#pragma unroll
  for (int i = 0; i < 6; i++) {
    int idx = tid + i * 256;
    int row = idx >> 4, seg = idx & 15;
    size_t src = (size_t)(kid[row] * kB + b) * kE + h * kD + seg * 8;
    cp16(sb + 17408 + row * kQKS + seg * 16, g_K16h + src);
    cp16(sb + 43520 + row * kQKS + seg * 16, g_K16l + src);
  }
  asm volatile("cp.async.commit_group;");
  asm volatile("cp.async.wait_group 0;");
  __syncthreads();

  // scores: warp w -> m-half mh = w>>2 (16 rows), n-group ng = w&3
  {
    int mh = w >> 2, ng = w & 3;
    float acc[3][4];
#pragma unroll
    for (int nt = 0; nt < 3; nt++)
#pragma unroll
      for (int q = 0; q < 4; q++) acc[nt][q] = 0.f;
#pragma unroll
    for (int ks = 0; ks < 8; ks++) {
      uint32_t a_h[4], a_l[4], b_h[3][2], b_l[3][2];
      uint32_t aoff = ks * 32 + (lane >> 4) * 16;
      uint32_t boff = ks * 32 + ((lane >> 3) & 1) * 16;
      uint32_t ra = (mh * 16 + (lane & 15)) * kQKS + aoff;
      ldsm_x4(a_h, sb + ra);
      ldsm_x4(a_l, sb + 8704 + ra);
#pragma unroll
      for (int nt = 0; nt < 3; nt++) {
        uint32_t rb = (ng * 24 + nt * 8 + (lane & 7)) * kQKS + boff;
        ldsm_x2(b_h[nt], sb + 17408 + rb);
        ldsm_x2(b_l[nt], sb + 43520 + rb);
      }
#pragma unroll
      for (int nt = 0; nt < 3; nt++) {
        mma16816(acc[nt], a_h, b_h[nt]);
        mma16816(acc[nt], a_l, b_h[nt]);
        mma16816(acc[nt], a_h, b_l[nt]);
      }
    }
#pragma unroll
    for (int nt = 0; nt < 3; nt++) {
      int l0 = mh * 16 + (lane >> 2);
      int m = ng * 24 + nt * 8 + (lane & 3) * 2;
      *(float2*)&sc[l0 * kSCS + m] = {acc[nt][0], acc[nt][1]};
      *(float2*)&sc[(l0 + 8) * kSCS + m] = {acc[nt][2], acc[nt][3]};
    }
  }
  __syncthreads();

#pragma unroll
  for (int i = 0; i < 6; i++) {
    int idx = tid + i * 256;
    int row = idx >> 4, seg = idx & 15;
    size_t src = (size_t)(kid[row] * kB + b) * kE + h * kD + seg * 8;
    cp16(sb + 17408 + row * kQKS + seg * 16, g_V16h + src);
    cp16(sb + 43520 + row * kQKS + seg * 16, g_V16l + src);
  }
  asm volatile("cp.async.commit_group;");

  {
    __nv_bfloat16* ph = (__nv_bfloat16*)(smb + 82432);
    __nv_bfloat16* pl = (__nv_bfloat16*)(smb + 89088);
#pragma unroll
    for (int rr = 0; rr < 4; rr++) {
      int l = w * 4 + rr;
      int myqh = qhh[l], myqid = qid[l];
      const unsigned* mw = g_mask + (size_t)(brho * kC + oc2[l]) * (kT / 32);
      float v[3];
#pragma unroll
      for (int j = 0; j < 3; j++) {
        int m = lane + 32 * j;
        float s = sc[l * kSCS + m];
        int id = kid[m];
        if (myqh != khh[m]) s -= kInfM;
        if (myqid == id) s -= kBigM;
        if ((mw[id >> 5] >> (id & 31)) & 1u) s -= kLog2;
        v[j] = s;
      }
      float mx = fmaxf(v[0], fmaxf(v[1], v[2]));
      for (int off = 16; off; off >>= 1)
        mx = fmaxf(mx, __shfl_xor_sync(0xffffffffu, mx, off));
      float ssum = 0.f;
#pragma unroll
      for (int j = 0; j < 3; j++) {
        int m = lane + 32 * j;
        float e = expf(v[j] - mx);
        ssum += e;
        __nv_bfloat16 hh, ll;
        split_bf16(e, hh, ll);
        ph[l * (kPS / 2) + m] = hh;
        pl[l * (kPS / 2) + m] = ll;
      }
      for (int off = 16; off; off >>= 1)
        ssum += __shfl_xor_sync(0xffffffffu, ssum, off);
      if (lane == 0) {
        rinv[l] = 1.0f / ssum;
        rowz[l] = mx + logf(ssum);
      }
    }
  }
  asm volatile("cp.async.wait_group 0;");
  __syncthreads();

  {
    float acc[2][2][4];
#pragma unroll
    for (int mt = 0; mt < 2; mt++)
#pragma unroll
      for (int nt = 0; nt < 2; nt++)
#pragma unroll
        for (int q = 0; q < 4; q++) acc[mt][nt][q] = 0.f;
#pragma unroll
    for (int ks = 0; ks < 6; ks++) {
      uint32_t a_h[2][4], a_l[2][4], b_h[2][2], b_l[2][2];
      uint32_t aoff = ks * 32 + (lane >> 4) * 16;
#pragma unroll
      for (int mt = 0; mt < 2; mt++) {
        uint32_t ra = (mt * 16 + (lane & 15)) * kPS + aoff;
        ldsm_x4(a_h[mt], sb + 82432 + ra);
        ldsm_x4(a_l[mt], sb + 89088 + ra);
      }
#pragma unroll
      for (int nt = 0; nt < 2; nt++) {
        uint32_t rb = (ks * 16 + (lane & 15)) * kQKS + (w * 16 + nt * 8) * 2;
        ldsm_x2t(b_h[nt], sb + 17408 + rb);
        ldsm_x2t(b_l[nt], sb + 43520 + rb);
      }
#pragma unroll
      for (int mt = 0; mt < 2; mt++)
#pragma unroll
        for (int nt = 0; nt < 2; nt++) {
          mma16816(acc[mt][nt], a_h[mt], b_h[nt]);
          mma16816(acc[mt][nt], a_l[mt], b_h[nt]);
          mma16816(acc[mt][nt], a_h[mt], b_l[nt]);
        }
    }
#pragma unroll
    for (int mt = 0; mt < 2; mt++)
#pragma unroll
      for (int nt = 0; nt < 2; nt++) {
        int l0 = mt * 16 + (lane >> 2);
        int l1 = l0 + 8;
        int n = w * 16 + nt * 8 + (lane & 3) * 2;
        float ri0 = rinv[l0], ri1 = rinv[l1];
        *(float2*)(g_o + (size_t)(brh * kT + qid[l0]) * kD + n) = {
            acc[mt][nt][0] * ri0, acc[mt][nt][1] * ri0};
        *(float2*)(g_o + (size_t)(brh * kT + qid[l1]) * kD + n) = {
            acc[mt][nt][2] * ri1, acc[mt][nt][3] * ri1};
      }
  }
  if (tid < 32) g_z[brh * kT + qid[tid]] = rowz[tid];
}

// ---------------- combine rounds (+ fused bf16 hi/lo split) ----------------
__global__ __launch_bounds__(256) void combine_kernel() {
  int idx = blockIdx.x * 256 + threadIdx.x;
  int d = idx & 127;
  int t = (idx >> 7) & (kT - 1);
  int h = (idx >> 18) & 7;
  int b = idx >> 21;
  int i0 = ((b * kR + 0) * kH + h) * kT + t;
  int i1 = ((b * kR + 1) * kH + h) * kT + t;
  float z0 = g_z[i0], z1 = g_z[i1];
  float m = fmaxf(z0, z1);
  float e0 = expf(z0 - m), e1 = expf(z1 - m);
  float inv = 1.0f / (e0 + e1);
  float val =
      (e0 * g_o[(size_t)i0 * kD + d] + e1 * g_o[(size_t)i1 * kD + d]) * inv;
  __nv_bfloat16 hi, lo;
  split_bf16(val, hi, lo);
  size_t o = (size_t)(t * kB + b) * kE + h * kD + d;
  g_Ahi[o] = hi;
  g_Alo[o] = lo;
}

// ---------------- launch ----------------
extern "C" void kernel_launch(void* const* d_in, const int* in_sizes, int n_in,
                              void* d_out, int out_size) {
  (void)in_sizes;
  (void)n_in;
  (void)out_size;
  const float* query = (const float*)d_in[0];
  const float* value = (const float*)d_in[2];
  const float* Wq = (const float*)d_in[3];
  const float* bq = (const float*)d_in[4];
  const float* Wv = (const float*)d_in[5];
  const float* bv = (const float*)d_in[6];
  const float* Wo = (const float*)d_in[7];
  const float* bo = (const float*)d_in[8];
  const float* hw = (const float*)d_in[9];
  float* out = (float*)d_out;

  float* pQF;
  cudaGetSymbolAddress((void**)&pQF, g_QF);
  __nv_bfloat16 *pAH, *pAL, *pViH, *pViL, *pV16h, *pV16l;
  cudaGetSymbolAddress((void**)&pAH, g_Ahi);
  cudaGetSymbolAddress((void**)&pAL, g_Alo);
  cudaGetSymbolAddress((void**)&pViH, g_Vihi);
  cudaGetSymbolAddress((void**)&pViL, g_Vilo);
  cudaGetSymbolAddress((void**)&pV16h, g_V16h);
  cudaGetSymbolAddress((void**)&pV16l, g_V16l);
  __nv_bfloat16 *pWqH, *pWqL, *pWvH, *pWvL, *pWoH, *pWoL;
  cudaGetSymbolAddress((void**)&pWqH, g_WqThi);
  cudaGetSymbolAddress((void**)&pWqL, g_WqTlo);
  cudaGetSymbolAddress((void**)&pWvH, g_WvThi);
  cudaGetSymbolAddress((void**)&pWvL, g_WvTlo);
  cudaGetSymbolAddress((void**)&pWoH, g_WoThi);
  cudaGetSymbolAddress((void**)&pWoL, g_WoTlo);

  cudaFuncSetAttribute(gemm_mma, cudaFuncAttributeMaxDynamicSharedMemorySize,
                       kGSmem);
  cudaFuncSetAttribute(attn_kernel, cudaFuncAttributeMaxDynamicSharedMemorySize,
                       ATTN_SMEM);
  cudaFuncSetAttribute(prepM_kernel, cudaFuncAttributeMaxDynamicSharedMemorySize,
                       kPrepSmem);

  static cudaStream_t s2 = nullptr;
  static cudaEvent_t evF = nullptr, evJ = nullptr;
  if (s2 == nullptr) {
    cudaStreamCreateWithFlags(&s2, cudaStreamNonBlocking);
    cudaEventCreateWithFlags(&evF, cudaEventDisableTiming);
    cudaEventCreateWithFlags(&evJ, cudaEventDisableTiming);
  }

  dim3 tgrid(32, 32);
  dim3 tblk(32, 8);
  dim3 ggrid(kE / 128, kTB / 128);

  bool use_side = (s2 != nullptr);
  cudaStream_t sv = use_side ? s2 : (cudaStream_t)0;

  if (use_side) {
    cudaEventRecord(evF, 0);
    cudaStreamWaitEvent(s2, evF, 0);
  }

  // ---- side chain: V projection FIRST (co-runs with Q GEMM), then prep ----
  wsplit_kernel<<<tgrid, tblk, 0, sv>>>(Wv, pWvH, pWvL);
  asplit_kernel<<<(kTB * kE / 4) / 256, 256, 0, sv>>>(value, pViH, pViL);
  gemm_mma<<<ggrid, 128, kGSmem, sv>>>(pViH, pViL, pWvH, pWvL, bv, nullptr,
                                       pV16h, pV16l);
  wsplit_kernel<<<tgrid, tblk, 0, sv>>>(Wo, pWoH, pWoL);
  prepM_kernel<<<dim3(16, 8), 128, kPrepSmem, sv>>>(Wq, bq, hw);
  linhash_kernel<<<kTB / 8, 256, 0, sv>>>(query);
  sort_kernel<<<kB * kR * kH, 256, 0, sv>>>();
  mask_kernel<<<kB * kR * kH * kC, 128, 0, sv>>>();

  // ---- main chain: Q projection ----
  wsplit_kernel<<<tgrid, tblk>>>(Wq, pWqH, pWqL);
  asplit_kernel<<<(kTB * kE / 4) / 256, 256>>>(query, pAH, pAL);
  gemm_mma<<<ggrid, 128, kGSmem>>>(pAH, pAL, pWqH, pWqL, bq, pQF, nullptr,
                                   nullptr);
  normalize_kernel<<<kTB, 256>>>();

  if (use_side) {
    cudaEventRecord(evJ, s2);
    cudaStreamWaitEvent((cudaStream_t)0, evJ, 0);
  }

  attn_kernel<<<kB * kR * kH * kC, 256, ATTN_SMEM>>>();
  combine_kernel<<<(kB * kH * kT * kD) / 256, 256>>>();
  gemm_mma<<<ggrid, 128, kGSmem>>>(pAH, pAL, pWoH, pWoL, bo, out, nullptr,
                                   nullptr);
}